// round 10
// baseline (speedup 1.0000x reference)
#include <cuda_runtime.h>
#include <cuda_bf16.h>
#include <math.h>
#include <stdint.h>

// Problem shapes (fixed by the dataset)
#define Bb 4
#define Tt 16
#define Ss 256
#define Dd 512
#define Nn 8
#define Mm (Bb * Ss)   // 1024 GEMM rows
#define Kk Dd          // 512  GEMM K
#define Nc (Dd * Nn)   // 4096 GEMM cols

// Role split / work decomposition
#define N_GEMM_CTAS 224
#define N_TOTAL_CTAS 592          // one wave at 4 CTAs/SM on 148 SMs
#define N_TILES 512               // 16 rb x 32 cb (tile 64x128)
#define N_CHUNKS 4096             // 128 cells each
#define FLAG_TARGET 32            // tiles per row-block

// ---------------------------------------------------------------------------
// Device scratch (no dynamic allocation allowed)
// ---------------------------------------------------------------------------
__device__ __align__(16) float         g_pop_rates[(size_t)Mm * Nc]; // 16.7 MB
__device__ __align__(16) __nv_bfloat16 g_Ehi[(size_t)Mm * Kk];       // [m][k]
__device__ __align__(16) __nv_bfloat16 g_Elo[(size_t)Mm * Kk];
__device__ __align__(16) __nv_bfloat16 g_Whi[(size_t)Kk * Nc];       // [k][n]
__device__ __align__(16) __nv_bfloat16 g_Wlo[(size_t)Kk * Nc];
__device__ int g_flags[16];
__device__ int g_tile_ticket;
__device__ int g_chunk_ticket;

// ---------------------------------------------------------------------------
// Fused bf16 hi/lo split conversion for E and W; also resets tickets/flags.
// ---------------------------------------------------------------------------
#define E_F4 ((Mm * Kk) / 4)      // 131072
#define W_F4 ((Kk * Nc) / 4)      // 524288

__device__ __forceinline__ void split4(float4 v, ushort4& hi, ushort4& lo) {
    __nv_bfloat16 h;
    h = __float2bfloat16(v.x); hi.x = __bfloat16_as_ushort(h);
    lo.x = __bfloat16_as_ushort(__float2bfloat16(v.x - __bfloat162float(h)));
    h = __float2bfloat16(v.y); hi.y = __bfloat16_as_ushort(h);
    lo.y = __bfloat16_as_ushort(__float2bfloat16(v.y - __bfloat162float(h)));
    h = __float2bfloat16(v.z); hi.z = __bfloat16_as_ushort(h);
    lo.z = __bfloat16_as_ushort(__float2bfloat16(v.z - __bfloat162float(h)));
    h = __float2bfloat16(v.w); hi.w = __bfloat16_as_ushort(h);
    lo.w = __bfloat16_as_ushort(__float2bfloat16(v.w - __bfloat162float(h)));
}

__global__ __launch_bounds__(256) void conv_kernel(const float* __restrict__ E,
                                                   const float* __restrict__ W) {
    if (blockIdx.x == 0 && threadIdx.x < 18) {
        if (threadIdx.x < 16) g_flags[threadIdx.x] = 0;
        else if (threadIdx.x == 16) g_tile_ticket = 0;
        else g_chunk_ticket = 0;
    }
    int i = blockIdx.x * 256 + threadIdx.x;
    if (i < E_F4) {
        float4 v = ((const float4*)E)[i];
        ushort4 hi, lo;
        split4(v, hi, lo);
        ((ushort4*)g_Ehi)[i] = hi;
        ((ushort4*)g_Elo)[i] = lo;
    } else {
        int j = i - E_F4;
        if (j < W_F4) {
            float4 v = ((const float4*)W)[j];
            ushort4 hi, lo;
            split4(v, hi, lo);
            ((ushort4*)g_Whi)[j] = hi;
            ((ushort4*)g_Wlo)[j] = lo;
        }
    }
}

// ---------------------------------------------------------------------------
// GEMM pieces (3-term Markidis split, tile 64x128, BK=32, 2-stage cp.async)
// ---------------------------------------------------------------------------
#define BM 64
#define BN 128
#define BK 32
#define NK (Kk / BK)          // 16 iterations

#define A_PITCH 40
#define B_PITCH 136
#define A_BYTES (BM * A_PITCH * 2)   // 5120
#define B_BYTES (BK * B_PITCH * 2)   // 8704
#define ST_AH 0
#define ST_AL A_BYTES
#define ST_BH (2 * A_BYTES)
#define ST_BL (2 * A_BYTES + B_BYTES)
#define STAGE_BYTES (2 * A_BYTES + 2 * B_BYTES)   // 27648
#define GEMM_SMEM (2 * STAGE_BYTES)               // 55296

__device__ __forceinline__ uint32_t smem_u32(const void* p) {
    uint32_t a;
    asm("{ .reg .u64 t; cvta.to.shared.u64 t, %1; cvt.u32.u64 %0, t; }"
        : "=r"(a) : "l"(p));
    return a;
}
__device__ __forceinline__ void cp16(uint32_t dst, const void* src) {
    asm volatile("cp.async.cg.shared.global [%0], [%1], 16;"
                 :: "r"(dst), "l"(src) : "memory");
}
__device__ __forceinline__ void ldsm_x4(uint32_t* r, uint32_t addr) {
    asm volatile("ldmatrix.sync.aligned.m8n8.x4.shared.b16 {%0,%1,%2,%3}, [%4];"
                 : "=r"(r[0]), "=r"(r[1]), "=r"(r[2]), "=r"(r[3]) : "r"(addr));
}
__device__ __forceinline__ void ldsm_x4t(uint32_t* r, uint32_t addr) {
    asm volatile("ldmatrix.sync.aligned.m8n8.x4.trans.shared.b16 {%0,%1,%2,%3}, [%4];"
                 : "=r"(r[0]), "=r"(r[1]), "=r"(r[2]), "=r"(r[3]) : "r"(addr));
}
__device__ __forceinline__ void mma16816(float* d, const uint32_t* a, const uint32_t* b) {
    asm volatile(
        "mma.sync.aligned.m16n8k16.row.col.f32.bf16.bf16.f32 "
        "{%0,%1,%2,%3}, {%4,%5,%6,%7}, {%8,%9}, {%0,%1,%2,%3};"
        : "+f"(d[0]), "+f"(d[1]), "+f"(d[2]), "+f"(d[3])
        : "r"(a[0]), "r"(a[1]), "r"(a[2]), "r"(a[3]), "r"(b[0]), "r"(b[1]));
}

__device__ void gemm_tile(char* smem, const float* __restrict__ bias,
                          int bm, int bn) {
    const uint32_t sbase = smem_u32(smem);
    const int tid = threadIdx.x;
    const int wid = tid >> 5;
    const int ln = tid & 31;
    const int warp_m = wid & 1;
    const int warp_n = wid >> 1;

    const int a_row0 = tid >> 2, a_seg = tid & 3;
    const int a_row1 = a_row0 + 32;
    const int b_row0 = tid >> 4, b_seg = tid & 15;

    auto load_stage = [&](int it, int p) {
        const int k0 = it * BK;
        const uint32_t st = sbase + p * STAGE_BYTES;
        {
            const size_t g0 = (size_t)(bm + a_row0) * Kk + k0 + a_seg * 8;
            const size_t g1 = (size_t)(bm + a_row1) * Kk + k0 + a_seg * 8;
            const uint32_t s0 = st + ST_AH + a_row0 * (A_PITCH * 2) + a_seg * 16;
            const uint32_t s1 = st + ST_AH + a_row1 * (A_PITCH * 2) + a_seg * 16;
            cp16(s0, g_Ehi + g0);
            cp16(s1, g_Ehi + g1);
            cp16(s0 + (ST_AL - ST_AH), g_Elo + g0);
            cp16(s1 + (ST_AL - ST_AH), g_Elo + g1);
        }
#pragma unroll
        for (int r = 0; r < 4; r++) {
            const int brow = b_row0 + r * 8;
            const size_t g = (size_t)(k0 + brow) * Nc + bn + b_seg * 8;
            const uint32_t sm = st + ST_BH + brow * (B_PITCH * 2) + b_seg * 16;
            cp16(sm, g_Whi + g);
            cp16(sm + (ST_BL - ST_BH), g_Wlo + g);
        }
        asm volatile("cp.async.commit_group;" ::: "memory");
    };

    float acc[2][8][4];
#pragma unroll
    for (int i = 0; i < 2; i++)
#pragma unroll
        for (int n = 0; n < 8; n++)
#pragma unroll
            for (int c = 0; c < 4; c++) acc[i][n][c] = 0.0f;

    const int lm_row = ln & 15;
    const int lm_half = ln >> 4;

    load_stage(0, 0);

    for (int it = 0; it < NK; it++) {
        const int p = it & 1;
        if (it + 1 < NK) load_stage(it + 1, p ^ 1);
        if (it + 1 < NK) { asm volatile("cp.async.wait_group 1;" ::: "memory"); }
        else             { asm volatile("cp.async.wait_group 0;" ::: "memory"); }
        __syncthreads();

        const uint32_t st = sbase + p * STAGE_BYTES;
        const uint32_t a_hi = st + ST_AH, a_lo = st + ST_AL;
        const uint32_t b_hi = st + ST_BH, b_lo = st + ST_BL;

#pragma unroll
        for (int j = 0; j < 2; j++) {
            uint32_t ah[2][4], al[2][4], bh[8][2], bl[8][2];
#pragma unroll
            for (int i = 0; i < 2; i++) {
                const uint32_t off =
                    (uint32_t)(warp_m * 32 + i * 16 + lm_row) * (A_PITCH * 2)
                    + (uint32_t)(j * 16 + lm_half * 8) * 2;
                ldsm_x4(ah[i], a_hi + off);
                ldsm_x4(al[i], a_lo + off);
            }
#pragma unroll
            for (int p4 = 0; p4 < 4; p4++) {
                const uint32_t off =
                    (uint32_t)(j * 16 + lm_row) * (B_PITCH * 2)
                    + (uint32_t)(warp_n * 64 + p4 * 16 + lm_half * 8) * 2;
                uint32_t r[4];
                ldsm_x4t(r, b_hi + off);
                bh[2 * p4][0] = r[0]; bh[2 * p4][1] = r[1];
                bh[2 * p4 + 1][0] = r[2]; bh[2 * p4 + 1][1] = r[3];
                ldsm_x4t(r, b_lo + off);
                bl[2 * p4][0] = r[0]; bl[2 * p4][1] = r[1];
                bl[2 * p4 + 1][0] = r[2]; bl[2 * p4 + 1][1] = r[3];
            }
#pragma unroll
            for (int i = 0; i < 2; i++)
#pragma unroll
                for (int n = 0; n < 8; n++) {
                    mma16816(acc[i][n], ah[i], bh[n]);
                    mma16816(acc[i][n], ah[i], bl[n]);
                    mma16816(acc[i][n], al[i], bh[n]);
                }
        }
        __syncthreads();
    }

    // Epilogue: bias + sigmoid -> g_pop_rates
    const int er = ln >> 2;
    const int ec = (ln & 3) * 2;
#pragma unroll
    for (int i = 0; i < 2; i++) {
        const int row0 = bm + warp_m * 32 + i * 16 + er;
#pragma unroll
        for (int n = 0; n < 8; n++) {
            const int col = bn + warp_n * 64 + n * 8 + ec;
            const float b0 = __ldg(bias + col);
            const float b1 = __ldg(bias + col + 1);
            float2 v0, v1;
            v0.x = 1.0f / (1.0f + expf(-(acc[i][n][0] + b0)));
            v0.y = 1.0f / (1.0f + expf(-(acc[i][n][1] + b1)));
            v1.x = 1.0f / (1.0f + expf(-(acc[i][n][2] + b0)));
            v1.y = 1.0f / (1.0f + expf(-(acc[i][n][3] + b1)));
            *(float2*)(g_pop_rates + (size_t)row0 * Nc + col) = v0;
            *(float2*)(g_pop_rates + (size_t)(row0 + 8) * Nc + col) = v1;
        }
    }
}

// ---------------------------------------------------------------------------
// Accurate fp32 sin (Cody-Waite + degree-9 minimax); fast-math immune.
// ---------------------------------------------------------------------------
__device__ __forceinline__ float my_sinf(float x) {
    const float INV_PI = 0.318309886183790672f;
    const float PI_HI = 3.14159274101257324f;
    const float PI_LO = -8.74227765734758577e-08f;
    float kf = rintf(x * INV_PI);
    float r = fmaf(-kf, PI_HI, x);
    r = fmaf(-kf, PI_LO, r);
    float s = r * r;
    float p = fmaf(s, 2.6083159809786593e-06f, -1.9810690719168633e-04f);
    p = fmaf(s, p, 8.3330785855650902e-03f);
    p = fmaf(s, p, -1.6666659712791443e-01f);
    float res = fmaf(r * s, p, r);
    int k = (int)kf;
    return (k & 1) ? -res : res;
}

// ---------------------------------------------------------------------------
// Encode one 128-cell chunk (cell = ch*128 + tid), loop over T=16.
// ---------------------------------------------------------------------------
__device__ void encode_chunk(
    int ch,
    const float* __restrict__ emb, const float* __restrict__ noise,
    const float* __restrict__ freq_bands, const float* __restrict__ enc_w,
    const float* __restrict__ rate_rand, const float* __restrict__ pop_rand,
    float* __restrict__ out)
{
    const int idx = ch * 128 + threadIdx.x;
    const int d = idx & (Dd - 1);
    const int s = (idx >> 9) & (Ss - 1);
    const int b = idx >> 17;

    float w0 = enc_w[0], w1 = enc_w[1], w2 = enc_w[2], w3 = enc_w[3];
    {
        float mx = fmaxf(fmaxf(w0, w1), fmaxf(w2, w3));
        float e0 = expf(w0 - mx), e1 = expf(w1 - mx);
        float e2 = expf(w2 - mx), e3 = expf(w3 - mx);
        float inv = 1.0f / (e0 + e1 + e2 + e3);
        w0 = e0 * inv; w1 = e1 * inv; w2 = e2 * inv; w3 = e3 * inv;
    }

    const float e = emb[idx];
    const float nz = noise[idx];
    const float sig = 1.0f / (1.0f + expf(-e));
    float rate = sig * 0.9f + 0.05f + nz * 0.1f;
    rate = fminf(fmaxf(rate, 0.0f), 1.0f);
    const int st = (int)(sig * 15.0f);
    const float phase = sig * 6.28318530717958647692f;
    const float freq = freq_bands[d];

    const float4* prp = (const float4*)(g_pop_rates + (size_t)idx * Nn);
    const float4 pr0 = prp[0];
    const float4 pr1 = prp[1];

    const float tstep = 6.28318530717958647692f / 15.0f;
    const size_t base = (((size_t)b * Tt) * Ss + s) * Dd + d;
#pragma unroll 4
    for (int t = 0; t < Tt; t++) {
        const size_t o = base + (size_t)t * (Ss * Dd);
        const float rr = __ldcs(rate_rand + o);
        const float4* pp = (const float4*)(pop_rand + o * Nn);
        const float4 q0 = __ldcs(pp);
        const float4 q1 = __ldcs(pp + 1);
        int cnt = (q0.x < pr0.x) + (q0.y < pr0.y) + (q0.z < pr0.z) + (q0.w < pr0.w)
                + (q1.x < pr1.x) + (q1.y < pr1.y) + (q1.z < pr1.z) + (q1.w < pr1.w);

        const float wave = my_sinf(fmaf(freq, (float)t * tstep, phase));

        float val = w0 * ((rr < rate) ? 1.0f : 0.0f)
                  + w1 * ((t == st) ? 1.0f : 0.0f)
                  + w2 * ((float)cnt * 0.125f)
                  + w3 * ((wave > 0.5f) ? 1.0f : 0.0f);
        __stcs(out + o, val);
    }
}

// ---------------------------------------------------------------------------
// Fused kernel: role-split CTAs. GEMM workers pull tile tickets and release
// per-row-block flags; encode workers pull chunk tickets gated on flags.
// Dynamic ticketing => deadlock-free under any CTA residency (GEMM workers
// occupy the lowest block IDs, so they are always in the first wave).
// ---------------------------------------------------------------------------
__global__ __launch_bounds__(128, 4) void fused_kernel(
    const float* __restrict__ bias,
    const float* __restrict__ emb, const float* __restrict__ noise,
    const float* __restrict__ freq_bands, const float* __restrict__ enc_w,
    const float* __restrict__ rate_rand, const float* __restrict__ pop_rand,
    float* __restrict__ out)
{
    extern __shared__ char smem[];
    __shared__ int sh_ticket;
    const int tid = threadIdx.x;

    if (blockIdx.x < N_GEMM_CTAS) {
        // ---- GEMM worker ----
        for (;;) {
            if (tid == 0) sh_ticket = atomicAdd(&g_tile_ticket, 1);
            __syncthreads();
            const int t = sh_ticket;
            if (t >= N_TILES) break;
            const int rb = t >> 5;        // rb-major tile order
            const int cb = t & 31;
            gemm_tile(smem, bias, rb * BM, cb * BN);
            __threadfence();
            __syncthreads();              // also protects sh_ticket reuse
            if (tid == 0) atomicAdd(&g_flags[rb], 1);
        }
    } else {
        // ---- Encode worker ----
        for (;;) {
            if (tid == 0) sh_ticket = atomicAdd(&g_chunk_ticket, 1);
            __syncthreads();
            const int ch = sh_ticket;
            if (ch >= N_CHUNKS) break;
            // Gate on this chunk's 64-row block of g_pop_rates.
            // Relaxed polling with generous backoff (cheap on L2), then one
            // acquire fence to order the subsequent pop_rates reads.
            if (tid == 0) {
                const int rb = ch >> 8;
                int v;
                for (;;) {
                    asm volatile("ld.relaxed.gpu.global.s32 %0, [%1];"
                                 : "=r"(v) : "l"(&g_flags[rb]) : "memory");
                    if (v >= FLAG_TARGET) break;
                    __nanosleep(512);
                }
                asm volatile("fence.acquire.gpu;" ::: "memory");
            }
            __syncthreads();
            encode_chunk(ch, emb, noise, freq_bands, enc_w,
                         rate_rand, pop_rand, out);
            __syncthreads();              // protects sh_ticket reuse
        }
    }
}

// ---------------------------------------------------------------------------
// Launch: conv -> fused (single stream)
// ---------------------------------------------------------------------------
extern "C" void kernel_launch(void* const* d_in, const int* in_sizes, int n_in,
                              void* d_out, int out_size) {
    const float* emb       = (const float*)d_in[0];
    const float* popW      = (const float*)d_in[1];
    const float* popb      = (const float*)d_in[2];
    const float* freq      = (const float*)d_in[3];
    const float* encw      = (const float*)d_in[4];
    const float* noise     = (const float*)d_in[5];
    const float* rate_rand = (const float*)d_in[6];
    const float* pop_rand  = (const float*)d_in[7];
    float* out = (float*)d_out;

    cudaFuncSetAttribute(fused_kernel,
                         cudaFuncAttributeMaxDynamicSharedMemorySize, GEMM_SMEM);

    conv_kernel<<<(E_F4 + W_F4) / 256, 256>>>(emb, popW);
    fused_kernel<<<N_TOTAL_CTAS, 128, GEMM_SMEM>>>(
        popb, emb, noise, freq, encw, rate_rand, pop_rand, out);
}

// round 11
// speedup vs baseline: 1.4046x; 1.4046x over previous
#include <cuda_runtime.h>
#include <cuda_bf16.h>
#include <math.h>
#include <stdint.h>

// Problem shapes (fixed by the dataset)
#define Bb 4
#define Tt 16
#define Ss 256
#define Dd 512
#define Nn 8
#define Mm (Bb * Ss)   // 1024 GEMM rows
#define Kk Dd          // 512  GEMM K
#define Nc (Dd * Nn)   // 4096 GEMM cols

// Work decomposition
#define N_TILES 1024              // 16 rb x 64 cb (tile 64x64)
#define FLAG_TARGET 64            // tiles per 64-row block
#define N_CHUNKS_W 16384          // 32-cell warp chunks (524288/32)

// ---------------------------------------------------------------------------
// Device scratch (no dynamic allocation allowed)
// ---------------------------------------------------------------------------
__device__ __align__(16) float         g_pop_rates[(size_t)Mm * Nc]; // 16.7 MB
__device__ __align__(16) __nv_bfloat16 g_Ehi[(size_t)Mm * Kk];       // [m][k]
__device__ __align__(16) __nv_bfloat16 g_Elo[(size_t)Mm * Kk];
__device__ __align__(16) __nv_bfloat16 g_Whi[(size_t)Kk * Nc];       // [k][n]
__device__ __align__(16) __nv_bfloat16 g_Wlo[(size_t)Kk * Nc];
__device__ int g_flags[16];
__device__ int g_tile_ticket;
__device__ int g_chunk_ticket;

// ---------------------------------------------------------------------------
// Fused bf16 hi/lo split conversion for E and W; also resets tickets/flags.
// ---------------------------------------------------------------------------
#define E_F4 ((Mm * Kk) / 4)      // 131072
#define W_F4 ((Kk * Nc) / 4)      // 524288

__device__ __forceinline__ void split4(float4 v, ushort4& hi, ushort4& lo) {
    __nv_bfloat16 h;
    h = __float2bfloat16(v.x); hi.x = __bfloat16_as_ushort(h);
    lo.x = __bfloat16_as_ushort(__float2bfloat16(v.x - __bfloat162float(h)));
    h = __float2bfloat16(v.y); hi.y = __bfloat16_as_ushort(h);
    lo.y = __bfloat16_as_ushort(__float2bfloat16(v.y - __bfloat162float(h)));
    h = __float2bfloat16(v.z); hi.z = __bfloat16_as_ushort(h);
    lo.z = __bfloat16_as_ushort(__float2bfloat16(v.z - __bfloat162float(h)));
    h = __float2bfloat16(v.w); hi.w = __bfloat16_as_ushort(h);
    lo.w = __bfloat16_as_ushort(__float2bfloat16(v.w - __bfloat162float(h)));
}

__global__ __launch_bounds__(256) void conv_kernel(const float* __restrict__ E,
                                                   const float* __restrict__ W) {
    if (blockIdx.x == 0 && threadIdx.x < 18) {
        if (threadIdx.x < 16) g_flags[threadIdx.x] = 0;
        else if (threadIdx.x == 16) g_tile_ticket = 0;
        else g_chunk_ticket = 0;
    }
    int i = blockIdx.x * 256 + threadIdx.x;
    if (i < E_F4) {
        float4 v = ((const float4*)E)[i];
        ushort4 hi, lo;
        split4(v, hi, lo);
        ((ushort4*)g_Ehi)[i] = hi;
        ((ushort4*)g_Elo)[i] = lo;
    } else {
        int j = i - E_F4;
        if (j < W_F4) {
            float4 v = ((const float4*)W)[j];
            ushort4 hi, lo;
            split4(v, hi, lo);
            ((ushort4*)g_Whi)[j] = hi;
            ((ushort4*)g_Wlo)[j] = lo;
        }
    }
}

// ---------------------------------------------------------------------------
// GEMM pieces: 64x64 tile, 8 warps (warp tile 16x32), BK=32, 2-stage cp.async.
// Group-local barriers only (bar.sync 1,256) so encode warps keep flowing.
// ---------------------------------------------------------------------------
#define BM 64
#define BN 64
#define BK 32
#define NK (Kk / BK)              // 16

#define A_PITCH_B 80              // 32+8 bf16 -> 80 bytes/row
#define B_PITCH_B 144             // 64+8 bf16 -> 144 bytes/row
#define A_BYTES (BM * A_PITCH_B)  // 5120
#define B_BYTES (BK * B_PITCH_B)  // 4608
#define ST_AH 0
#define ST_AL A_BYTES
#define ST_BH (2 * A_BYTES)
#define ST_BL (2 * A_BYTES + B_BYTES)
#define STAGE_BYTES (2 * A_BYTES + 2 * B_BYTES)   // 19456
#define FUSED_SMEM (2 * STAGE_BYTES)              // 38912

#define GBAR() asm volatile("bar.sync 1, 256;" ::: "memory")

__device__ __forceinline__ uint32_t smem_u32(const void* p) {
    uint32_t a;
    asm("{ .reg .u64 t; cvta.to.shared.u64 t, %1; cvt.u32.u64 %0, t; }"
        : "=r"(a) : "l"(p));
    return a;
}
__device__ __forceinline__ void cp16(uint32_t dst, const void* src) {
    asm volatile("cp.async.cg.shared.global [%0], [%1], 16;"
                 :: "r"(dst), "l"(src) : "memory");
}
__device__ __forceinline__ void ldsm_x4(uint32_t* r, uint32_t addr) {
    asm volatile("ldmatrix.sync.aligned.m8n8.x4.shared.b16 {%0,%1,%2,%3}, [%4];"
                 : "=r"(r[0]), "=r"(r[1]), "=r"(r[2]), "=r"(r[3]) : "r"(addr));
}
__device__ __forceinline__ void ldsm_x4t(uint32_t* r, uint32_t addr) {
    asm volatile("ldmatrix.sync.aligned.m8n8.x4.trans.shared.b16 {%0,%1,%2,%3}, [%4];"
                 : "=r"(r[0]), "=r"(r[1]), "=r"(r[2]), "=r"(r[3]) : "r"(addr));
}
__device__ __forceinline__ void mma16816(float* d, const uint32_t* a, const uint32_t* b) {
    asm volatile(
        "mma.sync.aligned.m16n8k16.row.col.f32.bf16.bf16.f32 "
        "{%0,%1,%2,%3}, {%4,%5,%6,%7}, {%8,%9}, {%0,%1,%2,%3};"
        : "+f"(d[0]), "+f"(d[1]), "+f"(d[2]), "+f"(d[3])
        : "r"(a[0]), "r"(a[1]), "r"(a[2]), "r"(a[3]), "r"(b[0]), "r"(b[1]));
}

__device__ void gemm_tile(char* smem, const float* __restrict__ bias,
                          int bm, int bn) {
    const uint32_t sbase = smem_u32(smem);
    const int tid = threadIdx.x;       // 0..255 (GEMM group only)
    const int wid = tid >> 5;          // 0..7
    const int ln = tid & 31;
    const int warp_m = wid & 3;        // 16-row band
    const int warp_n = wid >> 2;       // 32-col half

    const int a_row = tid >> 2, a_seg = tid & 3;   // 64 rows x 4 segs
    const int b_row = tid >> 3, b_seg = tid & 7;   // 32 rows x 8 segs

    auto load_stage = [&](int it, int p) {
        const int k0 = it * BK;
        const uint32_t st = sbase + p * STAGE_BYTES;
        {
            const size_t g = (size_t)(bm + a_row) * Kk + k0 + a_seg * 8;
            const uint32_t s = st + ST_AH + a_row * A_PITCH_B + a_seg * 16;
            cp16(s, g_Ehi + g);
            cp16(s + (ST_AL - ST_AH), g_Elo + g);
        }
        {
            const size_t g = (size_t)(k0 + b_row) * Nc + bn + b_seg * 8;
            const uint32_t s = st + ST_BH + b_row * B_PITCH_B + b_seg * 16;
            cp16(s, g_Whi + g);
            cp16(s + (ST_BL - ST_BH), g_Wlo + g);
        }
        asm volatile("cp.async.commit_group;" ::: "memory");
    };

    float acc[4][4];
#pragma unroll
    for (int n = 0; n < 4; n++)
#pragma unroll
        for (int c = 0; c < 4; c++) acc[n][c] = 0.0f;

    const int lm_row = ln & 15;
    const int lm_half = ln >> 4;

    load_stage(0, 0);

    for (int it = 0; it < NK; it++) {
        const int p = it & 1;
        if (it + 1 < NK) load_stage(it + 1, p ^ 1);
        if (it + 1 < NK) { asm volatile("cp.async.wait_group 1;" ::: "memory"); }
        else             { asm volatile("cp.async.wait_group 0;" ::: "memory"); }
        GBAR();

        const uint32_t st = sbase + p * STAGE_BYTES;
        const uint32_t a_hi = st + ST_AH, a_lo = st + ST_AL;
        const uint32_t b_hi = st + ST_BH, b_lo = st + ST_BL;

#pragma unroll
        for (int j = 0; j < 2; j++) {
            uint32_t ah[4], al[4], bh[4][2], bl[4][2];
            {
                const uint32_t off =
                    (uint32_t)(warp_m * 16 + lm_row) * A_PITCH_B
                    + (uint32_t)(j * 16 + lm_half * 8) * 2;
                ldsm_x4(ah, a_hi + off);
                ldsm_x4(al, a_lo + off);
            }
#pragma unroll
            for (int p4 = 0; p4 < 2; p4++) {
                const uint32_t off =
                    (uint32_t)(j * 16 + lm_row) * B_PITCH_B
                    + (uint32_t)(warp_n * 32 + p4 * 16 + lm_half * 8) * 2;
                uint32_t r[4];
                ldsm_x4t(r, b_hi + off);
                bh[2 * p4][0] = r[0]; bh[2 * p4][1] = r[1];
                bh[2 * p4 + 1][0] = r[2]; bh[2 * p4 + 1][1] = r[3];
                ldsm_x4t(r, b_lo + off);
                bl[2 * p4][0] = r[0]; bl[2 * p4][1] = r[1];
                bl[2 * p4 + 1][0] = r[2]; bl[2 * p4 + 1][1] = r[3];
            }
#pragma unroll
            for (int n = 0; n < 4; n++) {
                mma16816(acc[n], ah, bh[n]);
                mma16816(acc[n], ah, bl[n]);
                mma16816(acc[n], al, bh[n]);
            }
        }
        GBAR();
    }

    // Epilogue: bias + sigmoid -> g_pop_rates
    const int er = ln >> 2;
    const int ec = (ln & 3) * 2;
    const int row0 = bm + warp_m * 16 + er;
#pragma unroll
    for (int n = 0; n < 4; n++) {
        const int col = bn + warp_n * 32 + n * 8 + ec;
        const float b0 = __ldg(bias + col);
        const float b1 = __ldg(bias + col + 1);
        float2 v0, v1;
        v0.x = 1.0f / (1.0f + expf(-(acc[n][0] + b0)));
        v0.y = 1.0f / (1.0f + expf(-(acc[n][1] + b1)));
        v1.x = 1.0f / (1.0f + expf(-(acc[n][2] + b0)));
        v1.y = 1.0f / (1.0f + expf(-(acc[n][3] + b1)));
        *(float2*)(g_pop_rates + (size_t)row0 * Nc + col) = v0;
        *(float2*)(g_pop_rates + (size_t)(row0 + 8) * Nc + col) = v1;
    }
}

// ---------------------------------------------------------------------------
// Accurate fp32 sin (Cody-Waite + degree-9 minimax); fast-math immune.
// ---------------------------------------------------------------------------
__device__ __forceinline__ float my_sinf(float x) {
    const float INV_PI = 0.318309886183790672f;
    const float PI_HI = 3.14159274101257324f;
    const float PI_LO = -8.74227765734758577e-08f;
    float kf = rintf(x * INV_PI);
    float r = fmaf(-kf, PI_HI, x);
    r = fmaf(-kf, PI_LO, r);
    float s = r * r;
    float p = fmaf(s, 2.6083159809786593e-06f, -1.9810690719168633e-04f);
    p = fmaf(s, p, 8.3330785855650902e-03f);
    p = fmaf(s, p, -1.6666659712791443e-01f);
    float res = fmaf(r * s, p, r);
    int k = (int)kf;
    return (k & 1) ? -res : res;
}

// ---------------------------------------------------------------------------
// Fused kernel: 1024 threads/CTA, 1 CTA/SM, grid=148 (one wave).
// Warps 0-7: GEMM group (tile tickets, group barriers, flag release).
// Warps 8-31: encode workers (32-cell warp tickets, flag-gated).
// ---------------------------------------------------------------------------
__global__ __launch_bounds__(1024, 1) void fused_kernel(
    const float* __restrict__ bias,
    const float* __restrict__ emb, const float* __restrict__ noise,
    const float* __restrict__ freq_bands, const float* __restrict__ enc_w,
    const float* __restrict__ rate_rand, const float* __restrict__ pop_rand,
    float* __restrict__ out)
{
    extern __shared__ char smem[];
    __shared__ int sh_t;
    const int tid = threadIdx.x;
    const int wid = tid >> 5;

    if (wid < 8) {
        // ---- GEMM group (256 threads) ----
        for (;;) {
            if (tid == 0) sh_t = atomicAdd(&g_tile_ticket, 1);
            GBAR();
            const int t = sh_t;
            if (t >= N_TILES) break;
            const int rb = t >> 6;        // rb-major: 64 col-tiles per rb
            const int cb = t & 63;
            gemm_tile(smem, bias, rb * BM, cb * BN);
            __threadfence();
            GBAR();                       // all stores fenced before release
            if (tid == 0) atomicAdd(&g_flags[rb], 1);
        }
    } else {
        // ---- Encode warp ----
        const int lane = tid & 31;

        float w0 = enc_w[0], w1 = enc_w[1], w2 = enc_w[2], w3 = enc_w[3];
        {
            float mx = fmaxf(fmaxf(w0, w1), fmaxf(w2, w3));
            float e0 = expf(w0 - mx), e1 = expf(w1 - mx);
            float e2 = expf(w2 - mx), e3 = expf(w3 - mx);
            float inv = 1.0f / (e0 + e1 + e2 + e3);
            w0 = e0 * inv; w1 = e1 * inv; w2 = e2 * inv; w3 = e3 * inv;
        }
        const float tstep = 6.28318530717958647692f / 15.0f;

        for (;;) {
            int ch = 0;
            if (lane == 0) ch = atomicAdd(&g_chunk_ticket, 1);
            ch = __shfl_sync(0xffffffffu, ch, 0);
            if (ch >= N_CHUNKS_W) break;

            // gate on this chunk's 64-row block of g_pop_rates
            if (lane == 0) {
                const int rb = ch >> 10;
                int v;
                for (;;) {
                    asm volatile("ld.relaxed.gpu.global.s32 %0, [%1];"
                                 : "=r"(v) : "l"(&g_flags[rb]) : "memory");
                    if (v >= FLAG_TARGET) break;
                    __nanosleep(256);
                }
            }
            __syncwarp();
            asm volatile("fence.acq_rel.gpu;" ::: "memory");

            const int idx = ch * 32 + lane;
            const int d = idx & (Dd - 1);
            const int s = (idx >> 9) & (Ss - 1);
            const int b = idx >> 17;

            const float e = emb[idx];
            const float nz = noise[idx];
            const float sig = 1.0f / (1.0f + expf(-e));
            float rate = sig * 0.9f + 0.05f + nz * 0.1f;
            rate = fminf(fmaxf(rate, 0.0f), 1.0f);
            const int st = (int)(sig * 15.0f);
            const float phase = sig * 6.28318530717958647692f;
            const float freq = freq_bands[d];

            const float4* prp = (const float4*)(g_pop_rates + (size_t)idx * Nn);
            const float4 pr0 = prp[0];
            const float4 pr1 = prp[1];

            const size_t base = (((size_t)b * Tt) * Ss + s) * Dd + d;
#pragma unroll 4
            for (int t = 0; t < Tt; t++) {
                const size_t o = base + (size_t)t * (Ss * Dd);
                const float rr = __ldcs(rate_rand + o);
                const float4* pp = (const float4*)(pop_rand + o * Nn);
                const float4 q0 = __ldcs(pp);
                const float4 q1 = __ldcs(pp + 1);
                int cnt = (q0.x < pr0.x) + (q0.y < pr0.y) + (q0.z < pr0.z) + (q0.w < pr0.w)
                        + (q1.x < pr1.x) + (q1.y < pr1.y) + (q1.z < pr1.z) + (q1.w < pr1.w);

                const float wave = my_sinf(fmaf(freq, (float)t * tstep, phase));

                float val = w0 * ((rr < rate) ? 1.0f : 0.0f)
                          + w1 * ((t == st) ? 1.0f : 0.0f)
                          + w2 * ((float)cnt * 0.125f)
                          + w3 * ((wave > 0.5f) ? 1.0f : 0.0f);
                __stcs(out + o, val);
            }
        }
    }
}

// ---------------------------------------------------------------------------
// Launch: conv -> fused (single stream, single wave)
// ---------------------------------------------------------------------------
extern "C" void kernel_launch(void* const* d_in, const int* in_sizes, int n_in,
                              void* d_out, int out_size) {
    const float* emb       = (const float*)d_in[0];
    const float* popW      = (const float*)d_in[1];
    const float* popb      = (const float*)d_in[2];
    const float* freq      = (const float*)d_in[3];
    const float* encw      = (const float*)d_in[4];
    const float* noise     = (const float*)d_in[5];
    const float* rate_rand = (const float*)d_in[6];
    const float* pop_rand  = (const float*)d_in[7];
    float* out = (float*)d_out;

    cudaFuncSetAttribute(fused_kernel,
                         cudaFuncAttributeMaxDynamicSharedMemorySize, FUSED_SMEM);

    conv_kernel<<<(E_F4 + W_F4) / 256, 256>>>(emb, popW);
    fused_kernel<<<148, 1024, FUSED_SMEM>>>(
        popb, emb, noise, freq, encw, rate_rand, pop_rand, out);
}

// round 12
// speedup vs baseline: 1.6215x; 1.1544x over previous
#include <cuda_runtime.h>
#include <cuda_bf16.h>
#include <math.h>
#include <stdint.h>

// Problem shapes (fixed by the dataset)
#define Bb 4
#define Tt 16
#define Ss 256
#define Dd 512
#define Nn 8
#define Mm (Bb * Ss)   // 1024 GEMM rows
#define Kk Dd          // 512  GEMM K
#define Nc (Dd * Nn)   // 4096 GEMM cols

// ---------------------------------------------------------------------------
// Device scratch (no dynamic allocation allowed)
// ---------------------------------------------------------------------------
__device__ __align__(16) float         g_pop_rates[(size_t)Mm * Nc]; // 16.7 MB
__device__ __align__(16) __nv_bfloat16 g_Ehi[(size_t)Mm * Kk];       // [m][k]
__device__ __align__(16) __nv_bfloat16 g_Elo[(size_t)Mm * Kk];
__device__ __align__(16) __nv_bfloat16 g_Whi[(size_t)Kk * Nc];       // [k][n]
__device__ __align__(16) __nv_bfloat16 g_Wlo[(size_t)Kk * Nc];

// ---------------------------------------------------------------------------
// Conversion: fp32 -> bf16 hi/lo split. 8 elems (2 float4) per thread,
// packed 16B stores. Values identical to scalar __float2bfloat16 path.
// ---------------------------------------------------------------------------
#define E_F4 ((Mm * Kk) / 4)      // 131072
#define W_F4 ((Kk * Nc) / 4)      // 524288
#define CONV_THREADS ((E_F4 + W_F4) / 2)   // 327680 -> 1280 blocks

__device__ __forceinline__ uint32_t pack_hi2(float a, float b) {
    uint32_t ha = (uint32_t)__bfloat16_as_ushort(__float2bfloat16(a));
    uint32_t hb = (uint32_t)__bfloat16_as_ushort(__float2bfloat16(b));
    return ha | (hb << 16);
}
__device__ __forceinline__ uint32_t pack_lo2(float a, float b) {
    float fa = __bfloat162float(__float2bfloat16(a));
    float fb = __bfloat162float(__float2bfloat16(b));
    uint32_t la = (uint32_t)__bfloat16_as_ushort(__float2bfloat16(a - fa));
    uint32_t lb = (uint32_t)__bfloat16_as_ushort(__float2bfloat16(b - fb));
    return la | (lb << 16);
}

__device__ __forceinline__ void conv8(const float4* __restrict__ src,
                                      uint4* __restrict__ dhi,
                                      uint4* __restrict__ dlo) {
    const float4 v0 = __ldcs(src);
    const float4 v1 = __ldcs(src + 1);
    uint4 h, l;
    h.x = pack_hi2(v0.x, v0.y); h.y = pack_hi2(v0.z, v0.w);
    h.z = pack_hi2(v1.x, v1.y); h.w = pack_hi2(v1.z, v1.w);
    l.x = pack_lo2(v0.x, v0.y); l.y = pack_lo2(v0.z, v0.w);
    l.z = pack_lo2(v1.x, v1.y); l.w = pack_lo2(v1.z, v1.w);
    __stcs(dhi, h);
    __stcs(dlo, l);
}

__global__ __launch_bounds__(256) void conv_kernel(const float* __restrict__ E,
                                                   const float* __restrict__ W) {
    const int t = blockIdx.x * 256 + threadIdx.x;       // 0..327679
    const int i = t * 2;                                 // float4 index
    if (i < E_F4) {
        conv8((const float4*)E + i, (uint4*)g_Ehi + t, (uint4*)g_Elo + t);
    } else {
        const int j = i - E_F4;
        const int tj = t - E_F4 / 2;
        conv8((const float4*)W + j, (uint4*)g_Whi + tj, (uint4*)g_Wlo + tj);
    }
}

// ---------------------------------------------------------------------------
// mma.sync bf16 GEMM (3-term Markidis split) + bias + sigmoid epilogue.
// CTA tile 128x128, BK=32, 8 warps (warp tile 32x64), 3-stage cp.async,
// 2 CTAs/SM (227.3 KB smem/SM) -> depth-2 lookahead + dual barrier domains.
// ---------------------------------------------------------------------------
#define BM 128
#define BN 128
#define BK 32
#define NK (Kk / BK)          // 16 iterations
#define STAGES 3

#define A_PITCH 40            // bf16 elems per A smem row (32 + 8 pad) -> 80 B
#define B_PITCH 136           // bf16 elems per B smem row (128 + 8 pad) -> 272 B
#define A_BYTES (BM * A_PITCH * 2)   // 10240
#define B_BYTES (BK * B_PITCH * 2)   // 8704
#define ST_AH 0
#define ST_AL A_BYTES
#define ST_BH (2 * A_BYTES)
#define ST_BL (2 * A_BYTES + B_BYTES)
#define STAGE_BYTES (2 * A_BYTES + 2 * B_BYTES)   // 37888
#define GEMM_SMEM (STAGES * STAGE_BYTES)          // 113664

__device__ __forceinline__ uint32_t smem_u32(const void* p) {
    uint32_t a;
    asm("{ .reg .u64 t; cvta.to.shared.u64 t, %1; cvt.u32.u64 %0, t; }"
        : "=r"(a) : "l"(p));
    return a;
}
__device__ __forceinline__ void cp16(uint32_t dst, const void* src) {
    asm volatile("cp.async.cg.shared.global [%0], [%1], 16;"
                 :: "r"(dst), "l"(src) : "memory");
}
__device__ __forceinline__ void ldsm_x4(uint32_t* r, uint32_t addr) {
    asm volatile("ldmatrix.sync.aligned.m8n8.x4.shared.b16 {%0,%1,%2,%3}, [%4];"
                 : "=r"(r[0]), "=r"(r[1]), "=r"(r[2]), "=r"(r[3]) : "r"(addr));
}
__device__ __forceinline__ void ldsm_x4t(uint32_t* r, uint32_t addr) {
    asm volatile("ldmatrix.sync.aligned.m8n8.x4.trans.shared.b16 {%0,%1,%2,%3}, [%4];"
                 : "=r"(r[0]), "=r"(r[1]), "=r"(r[2]), "=r"(r[3]) : "r"(addr));
}
__device__ __forceinline__ void mma16816(float* d, const uint32_t* a, const uint32_t* b) {
    asm volatile(
        "mma.sync.aligned.m16n8k16.row.col.f32.bf16.bf16.f32 "
        "{%0,%1,%2,%3}, {%4,%5,%6,%7}, {%8,%9}, {%0,%1,%2,%3};"
        : "+f"(d[0]), "+f"(d[1]), "+f"(d[2]), "+f"(d[3])
        : "r"(a[0]), "r"(a[1]), "r"(a[2]), "r"(a[3]), "r"(b[0]), "r"(b[1]));
}

__global__ __launch_bounds__(256, 2) void gemm_mma_kernel(const float* __restrict__ bias) {
    extern __shared__ char smem[];
    const uint32_t sbase = smem_u32(smem);
    const int tid = threadIdx.x;
    const int wid = tid >> 5;
    const int ln = tid & 31;
    const int warp_m = wid & 3;       // 4 warps along M (32 rows each)
    const int warp_n = wid >> 2;      // 2 warps along N (64 cols each)
    const int bm = blockIdx.y * BM;
    const int bn = blockIdx.x * BN;

    // --- cp.async tile loader thread mapping ---
    const int a_row0 = tid >> 2, a_seg = tid & 3;   // A: 512 chunks/array
    const int a_row1 = a_row0 + 64;
    const int b_row0 = tid >> 4, b_seg = tid & 15;  // B: 512 chunks/array
    const int b_row1 = b_row0 + 16;

    auto load_stage = [&](int it) {
        const int k0 = it * BK;
        const uint32_t st = sbase + (it % STAGES) * STAGE_BYTES;
        {
            const size_t g0 = (size_t)(bm + a_row0) * Kk + k0 + a_seg * 8;
            const size_t g1 = (size_t)(bm + a_row1) * Kk + k0 + a_seg * 8;
            const uint32_t s0 = st + ST_AH + a_row0 * (A_PITCH * 2) + a_seg * 16;
            const uint32_t s1 = st + ST_AH + a_row1 * (A_PITCH * 2) + a_seg * 16;
            cp16(s0, g_Ehi + g0);
            cp16(s1, g_Ehi + g1);
            cp16(s0 + (ST_AL - ST_AH), g_Elo + g0);
            cp16(s1 + (ST_AL - ST_AH), g_Elo + g1);
        }
        {
            const size_t g0 = (size_t)(k0 + b_row0) * Nc + bn + b_seg * 8;
            const size_t g1 = (size_t)(k0 + b_row1) * Nc + bn + b_seg * 8;
            const uint32_t s0 = st + ST_BH + b_row0 * (B_PITCH * 2) + b_seg * 16;
            const uint32_t s1 = st + ST_BH + b_row1 * (B_PITCH * 2) + b_seg * 16;
            cp16(s0, g_Whi + g0);
            cp16(s1, g_Whi + g1);
            cp16(s0 + (ST_BL - ST_BH), g_Wlo + g0);
            cp16(s1 + (ST_BL - ST_BH), g_Wlo + g1);
        }
        asm volatile("cp.async.commit_group;" ::: "memory");
    };

    float acc[2][8][4];
#pragma unroll
    for (int i = 0; i < 2; i++)
#pragma unroll
        for (int n = 0; n < 8; n++)
#pragma unroll
            for (int c = 0; c < 4; c++) acc[i][n][c] = 0.0f;

    const int lm_row = ln & 15;
    const int lm_half = ln >> 4;

    // Prologue: fill STAGES-1 buffers
    load_stage(0);
    load_stage(1);

    for (int it = 0; it < NK; it++) {
        __syncthreads();                 // all warps done with stage it-1
        if (it + 2 < NK) load_stage(it + 2);
        // wait until stage `it` has landed
        if (it < NK - 2)      { asm volatile("cp.async.wait_group 2;" ::: "memory"); }
        else if (it == NK - 2){ asm volatile("cp.async.wait_group 1;" ::: "memory"); }
        else                  { asm volatile("cp.async.wait_group 0;" ::: "memory"); }
        __syncthreads();

        const uint32_t st = sbase + (it % STAGES) * STAGE_BYTES;
        const uint32_t a_hi = st + ST_AH, a_lo = st + ST_AL;
        const uint32_t b_hi = st + ST_BH, b_lo = st + ST_BL;

#pragma unroll
        for (int j = 0; j < 2; j++) {          // k16 sub-steps within BK=32
            uint32_t ah[2][4], al[2][4], bh[8][2], bl[8][2];
#pragma unroll
            for (int i = 0; i < 2; i++) {
                const uint32_t off =
                    (uint32_t)(warp_m * 32 + i * 16 + lm_row) * (A_PITCH * 2)
                    + (uint32_t)(j * 16 + lm_half * 8) * 2;
                ldsm_x4(ah[i], a_hi + off);
                ldsm_x4(al[i], a_lo + off);
            }
#pragma unroll
            for (int p4 = 0; p4 < 4; p4++) {
                const uint32_t off =
                    (uint32_t)(j * 16 + lm_row) * (B_PITCH * 2)
                    + (uint32_t)(warp_n * 64 + p4 * 16 + lm_half * 8) * 2;
                uint32_t r[4];
                ldsm_x4t(r, b_hi + off);
                bh[2 * p4][0] = r[0]; bh[2 * p4][1] = r[1];
                bh[2 * p4 + 1][0] = r[2]; bh[2 * p4 + 1][1] = r[3];
                ldsm_x4t(r, b_lo + off);
                bl[2 * p4][0] = r[0]; bl[2 * p4][1] = r[1];
                bl[2 * p4 + 1][0] = r[2]; bl[2 * p4 + 1][1] = r[3];
            }
#pragma unroll
            for (int i = 0; i < 2; i++)
#pragma unroll
                for (int n = 0; n < 8; n++) {
                    mma16816(acc[i][n], ah[i], bh[n]);
                    mma16816(acc[i][n], ah[i], bl[n]);
                    mma16816(acc[i][n], al[i], bh[n]);
                }
        }
    }

    // Epilogue: bias + sigmoid -> g_pop_rates
    const int er = ln >> 2;
    const int ec = (ln & 3) * 2;
#pragma unroll
    for (int i = 0; i < 2; i++) {
        const int row0 = bm + warp_m * 32 + i * 16 + er;
#pragma unroll
        for (int n = 0; n < 8; n++) {
            const int col = bn + warp_n * 64 + n * 8 + ec;
            const float b0 = __ldg(bias + col);
            const float b1 = __ldg(bias + col + 1);
            float2 v0, v1;
            v0.x = 1.0f / (1.0f + expf(-(acc[i][n][0] + b0)));
            v0.y = 1.0f / (1.0f + expf(-(acc[i][n][1] + b1)));
            v1.x = 1.0f / (1.0f + expf(-(acc[i][n][2] + b0)));
            v1.y = 1.0f / (1.0f + expf(-(acc[i][n][3] + b1)));
            *(float2*)(g_pop_rates + (size_t)row0 * Nc + col) = v0;
            *(float2*)(g_pop_rates + (size_t)(row0 + 8) * Nc + col) = v1;
        }
    }
}

// ---------------------------------------------------------------------------
// Accurate fp32 sin (Cody-Waite + degree-9 minimax); fast-math immune.
// ---------------------------------------------------------------------------
__device__ __forceinline__ float my_sinf(float x) {
    const float INV_PI = 0.318309886183790672f;
    const float PI_HI = 3.14159274101257324f;
    const float PI_LO = -8.74227765734758577e-08f;
    float kf = rintf(x * INV_PI);
    float r = fmaf(-kf, PI_HI, x);
    r = fmaf(-kf, PI_LO, r);
    float s = r * r;
    float p = fmaf(s, 2.6083159809786593e-06f, -1.9810690719168633e-04f);
    p = fmaf(s, p, 8.3330785855650902e-03f);
    p = fmaf(s, p, -1.6666659712791443e-01f);
    float res = fmaf(r * s, p, r);
    int k = (int)kf;
    return (k & 1) ? -res : res;
}

// ---------------------------------------------------------------------------
// Fused encoder: one thread per (b,s,d), loop over T=16, unroll 8 for MLP.
// ---------------------------------------------------------------------------
__global__ __launch_bounds__(256) void encode_kernel(
    const float* __restrict__ emb,
    const float* __restrict__ noise,
    const float* __restrict__ freq_bands,
    const float* __restrict__ enc_w,
    const float* __restrict__ rate_rand,
    const float* __restrict__ pop_rand,
    float* __restrict__ out)
{
    const int idx = blockIdx.x * 256 + threadIdx.x;
    const int d = idx & (Dd - 1);
    const int s = (idx >> 9) & (Ss - 1);
    const int b = idx >> 17;

    float w0 = enc_w[0], w1 = enc_w[1], w2 = enc_w[2], w3 = enc_w[3];
    {
        float mx = fmaxf(fmaxf(w0, w1), fmaxf(w2, w3));
        float e0 = expf(w0 - mx), e1 = expf(w1 - mx);
        float e2 = expf(w2 - mx), e3 = expf(w3 - mx);
        float inv = 1.0f / (e0 + e1 + e2 + e3);
        w0 = e0 * inv; w1 = e1 * inv; w2 = e2 * inv; w3 = e3 * inv;
    }

    const float e = emb[idx];
    const float nz = noise[idx];
    const float sig = 1.0f / (1.0f + expf(-e));
    float rate = sig * 0.9f + 0.05f + nz * 0.1f;
    rate = fminf(fmaxf(rate, 0.0f), 1.0f);
    const int st = (int)(sig * 15.0f);
    const float phase = sig * 6.28318530717958647692f;
    const float freq = freq_bands[d];

    const float4* prp = (const float4*)(g_pop_rates + (size_t)idx * Nn);
    const float4 pr0 = prp[0];
    const float4 pr1 = prp[1];

    const float tstep = 6.28318530717958647692f / 15.0f;
    const size_t base = (((size_t)b * Tt) * Ss + s) * Dd + d;
#pragma unroll 8
    for (int t = 0; t < Tt; t++) {
        const size_t o = base + (size_t)t * (Ss * Dd);
        const float rr = __ldcs(rate_rand + o);
        const float4* pp = (const float4*)(pop_rand + o * Nn);
        const float4 q0 = __ldcs(pp);
        const float4 q1 = __ldcs(pp + 1);
        int cnt = (q0.x < pr0.x) + (q0.y < pr0.y) + (q0.z < pr0.z) + (q0.w < pr0.w)
                + (q1.x < pr1.x) + (q1.y < pr1.y) + (q1.z < pr1.z) + (q1.w < pr1.w);

        const float wave = my_sinf(fmaf(freq, (float)t * tstep, phase));

        float val = w0 * ((rr < rate) ? 1.0f : 0.0f)
                  + w1 * ((t == st) ? 1.0f : 0.0f)
                  + w2 * ((float)cnt * 0.125f)
                  + w3 * ((wave > 0.5f) ? 1.0f : 0.0f);
        __stcs(out + o, val);
    }
}

// ---------------------------------------------------------------------------
// Launch (serial, single stream — concurrency schemes all regressed)
// ---------------------------------------------------------------------------
extern "C" void kernel_launch(void* const* d_in, const int* in_sizes, int n_in,
                              void* d_out, int out_size) {
    const float* emb       = (const float*)d_in[0];
    const float* popW      = (const float*)d_in[1];
    const float* popb      = (const float*)d_in[2];
    const float* freq      = (const float*)d_in[3];
    const float* encw      = (const float*)d_in[4];
    const float* noise     = (const float*)d_in[5];
    const float* rate_rand = (const float*)d_in[6];
    const float* pop_rand  = (const float*)d_in[7];
    float* out = (float*)d_out;

    cudaFuncSetAttribute(gemm_mma_kernel,
                         cudaFuncAttributeMaxDynamicSharedMemorySize, GEMM_SMEM);

    conv_kernel<<<CONV_THREADS / 256, 256>>>(emb, popW);
    gemm_mma_kernel<<<dim3(Nc / BN, Mm / BM), 256, GEMM_SMEM>>>(popb);
    encode_kernel<<<(Mm * Dd) / 256, 256>>>(emb, noise, freq, encw,
                                            rate_rand, pop_rand, out);
}